// round 1
// baseline (speedup 1.0000x reference)
#include <cuda_runtime.h>
#include <math.h>

#define P 7
#define C 512
#define H 38
#define W 38
#define NROI 128

__global__ void roipool_kernel(const float* __restrict__ x,
                               const float* __restrict__ rois,
                               float* __restrict__ out,
                               int total) {
    int idx = blockIdx.x * blockDim.x + threadIdx.x;
    if (idx >= total) return;

    // out layout: [n, c, ph, pw], pw fastest -> coalesced STG
    int pw = idx % P;
    int t  = idx / P;
    int ph = t % P;
    t /= P;
    int c  = t % C;
    int n  = t / C;

    // rois[n] = {y1, x1, y2, x2} in image coords
    const float4 r = __ldg(reinterpret_cast<const float4*>(rois) + n);
    int y1 = (int)floorf(r.x * 0.0625f);
    int x1 = (int)floorf(r.y * 0.0625f);
    int y2 = (int)floorf(r.z * 0.0625f);
    int x2 = (int)floorf(r.w * 0.0625f);

    int sh = y2 - y1 + 1;
    int sw = x2 - x1 + 1;

    // AdaptiveMaxPool bin: [lo + i*s/P, lo + ceil((i+1)*s/P))
    int hs = y1 + (ph * sh) / P;
    int he = y1 + ((ph + 1) * sh + P - 1) / P;
    int ws = x1 + (pw * sw) / P;
    int we = x1 + ((pw + 1) * sw + P - 1) / P;

    const float* __restrict__ xc = x + (long)c * (H * W);

    float m = -INFINITY;
    #pragma unroll 1
    for (int h = hs; h < he; ++h) {
        const float* __restrict__ row = xc + h * W;
        #pragma unroll 1
        for (int w = ws; w < we; ++w) {
            m = fmaxf(m, __ldg(row + w));
        }
    }
    out[idx] = m;
}

extern "C" void kernel_launch(void* const* d_in, const int* in_sizes, int n_in,
                              void* d_out, int out_size) {
    const float* x    = (const float*)d_in[0];   // [1, 512, 38, 38]
    const float* rois = (const float*)d_in[1];   // [128, 4]
    float* out        = (float*)d_out;           // [128, 512, 7, 7]

    int total = NROI * C * P * P;                // 3,211,264
    int threads = 256;
    int blocks = (total + threads - 1) / threads;
    roipool_kernel<<<blocks, threads>>>(x, rois, out, total);
}